// round 2
// baseline (speedup 1.0000x reference)
#include <cuda_runtime.h>
#include <math.h>
#include <stdint.h>

#define NTOK  65536
#define DHALF 384
#define DFULL 768
#define LSZ   64
#define HSZ   64
#define RSZ   8

// ---------------- device scratch (static; no allocations) ----------------
__device__ float g_Vlt[RSZ*HSZ*LSZ];            // normalized V-proj, [r][h][l]
__device__ int   g_cnt[RSZ];
__device__ float g_probsum[RSZ];
__device__ int   g_list[RSZ*NTOK];              // entry e = 2*n + slot
__device__ float g_gate[2*NTOK];                // gate weight per entry
__device__ float g_out[(size_t)2*NTOK*LSZ];     // gate-scaled softmax scores per entry

// ---------------- init ----------------
__global__ void init_kernel() {
    int t = threadIdx.x;
    if (t < RSZ) { g_cnt[t] = 0; g_probsum[t] = 0.f; }
}

// ---------------- Vl = l2norm(llm @ V_w[r] + V_b[r]); store transposed [r][h][l] ------
__global__ __launch_bounds__(64) void vl_kernel(const float* __restrict__ llm,
                                                const float* __restrict__ Vw,
                                                const float* __restrict__ Vb) {
    int l = blockIdx.x, r = blockIdx.y, h = threadIdx.x;
    __shared__ float lsm[DHALF];
    __shared__ float red[64];
    __shared__ float s_inv;
    for (int i = h; i < DHALF; i += 64) lsm[i] = llm[l*DHALF + i];
    __syncthreads();
    float acc = Vb[r*HSZ + h];
    const float* w = Vw + ((size_t)r*DHALF)*HSZ + h;
    #pragma unroll 8
    for (int d = 0; d < DHALF; d++) acc += lsm[d] * w[(size_t)d*HSZ];
    red[h] = acc*acc;
    __syncthreads();
    if (h == 0) {
        float ss = 0.f;
        #pragma unroll
        for (int i = 0; i < 64; i++) ss += red[i];
        s_inv = 1.f / fmaxf(sqrtf(ss), 1e-12f);
    }
    __syncthreads();
    g_Vlt[(r*HSZ + h)*LSZ + l] = acc * s_inv;
}

// ---------------- gate: logits, softmax, top-2, list build, aux sums ----------------
__global__ __launch_bounds__(256) void gate_kernel(const float* __restrict__ posts,
                                                   const float* __restrict__ reas,
                                                   const float* __restrict__ gw,
                                                   const float* __restrict__ gb) {
    __shared__ float wsm[RSZ*DFULL];   // [r][k]
    __shared__ float pblk[8][RSZ];
    int t = threadIdx.x, lane = t & 31, w = t >> 5;
    for (int idx = t; idx < RSZ*DFULL; idx += 256) {
        int k = idx >> 3, r = idx & 7;
        wsm[r*DFULL + k] = gw[idx];
    }
    if (lane < RSZ) pblk[w][lane] = 0.f;
    __syncthreads();

    for (int tok = 0; tok < 2; tok++) {
        int n = blockIdx.x*16 + w*2 + tok;
        float acc[RSZ];
        #pragma unroll
        for (int r = 0; r < RSZ; r++) acc[r] = 0.f;
        const float* xp = posts + (size_t)n*DHALF;
        const float* xr = reas  + (size_t)n*DHALF;
        #pragma unroll
        for (int i = 0; i < 12; i++) {
            int k = lane + 32*i;
            float xv = xp[k];
            #pragma unroll
            for (int r = 0; r < RSZ; r++) acc[r] += xv * wsm[r*DFULL + k];
        }
        #pragma unroll
        for (int i = 0; i < 12; i++) {
            int k = lane + 32*i;
            float xv = xr[k];
            #pragma unroll
            for (int r = 0; r < RSZ; r++) acc[r] += xv * wsm[r*DFULL + DHALF + k];
        }
        #pragma unroll
        for (int r = 0; r < RSZ; r++) {
            #pragma unroll
            for (int o = 16; o > 0; o >>= 1)
                acc[r] += __shfl_xor_sync(0xffffffffu, acc[r], o);
        }
        if (lane == 0) {
            float lg[RSZ];
            #pragma unroll
            for (int r = 0; r < RSZ; r++) lg[r] = acc[r] + gb[r];
            // top-2: strict >, earlier index wins ties (matches jax top_k)
            float v1 = -1e30f, v2 = -1e30f; int i1 = 0, i2 = 0;
            #pragma unroll
            for (int r = 0; r < RSZ; r++) {
                if (lg[r] > v1)      { v2 = v1; i2 = i1; v1 = lg[r]; i1 = r; }
                else if (lg[r] > v2) { v2 = lg[r]; i2 = r; }
            }
            float s = 0.f, p[RSZ];
            #pragma unroll
            for (int r = 0; r < RSZ; r++) { p[r] = expf(lg[r] - v1); s += p[r]; }
            float invs = 1.f / s;
            #pragma unroll
            for (int r = 0; r < RSZ; r++) pblk[w][r] += p[r]*invs;
            float g0 = 1.f / (1.f + expf(v2 - v1));
            g_gate[2*n]   = g0;
            g_gate[2*n+1] = 1.f - g0;
            int p0 = atomicAdd(&g_cnt[i1], 1); g_list[i1*NTOK + p0] = 2*n;
            int p1 = atomicAdd(&g_cnt[i2], 1); g_list[i2*NTOK + p1] = 2*n + 1;
        }
    }
    __syncthreads();
    if (t < RSZ) {
        float s = 0.f;
        #pragma unroll
        for (int wi = 0; wi < 8; wi++) s += pblk[wi][t];
        atomicAdd(&g_probsum[t], s);
    }
}

// ---------------- gathered projection + norm + score GEMM + softmax ----------------
// block 256 thr; tile = 128 entries x 64 cols; micro-tile: lane -> rows 4*lane..+3,
// warp w -> cols 8w..8w+7.  K=768 in 24 chunks of 32.
__global__ __launch_bounds__(256) void proj_kernel(const float* __restrict__ posts,
                                                   const float* __restrict__ reas,
                                                   const float* __restrict__ Uw,
                                                   const float* __restrict__ Ub) {
    int r = blockIdx.y;
    int cnt = g_cnt[r];
    int base = blockIdx.x * 128;
    if (base >= cnt) return;

    __shared__ union {
        struct { float Xs[32][128]; float Ws[32][64]; } m;   // k-major X tile
        struct { float Ust[64][128]; float Vs[32][64]; } e;
    } sh;
    __shared__ float pm[8][128];
    __shared__ float rn[128];
    __shared__ float mx[128];
    __shared__ int   el[128];
    __shared__ float gwv[128];

    int t = threadIdx.x, lane = t & 31, w = t >> 5;

    if (t < 128) {
        int i = base + t;
        int e = (i < cnt) ? g_list[r*NTOK + i] : g_list[r*NTOK + base];
        el[t] = e;
        gwv[t] = g_gate[e];
    }
    __syncthreads();

    float acc[4][8];
    #pragma unroll
    for (int i = 0; i < 4; i++)
        #pragma unroll
        for (int j = 0; j < 8; j++) acc[i][j] = 0.f;

    const float* UwR = Uw + (size_t)r*DFULL*HSZ;
    int ld_row  = t & 127;          // row this thread loads
    int ld_half = t >> 7;           // which 16-float half of the 32-chunk

    for (int c = 0; c < 24; c++) {
        // ---- load X chunk (gathered rows), store k-major Xs[k][row] ----
        {
            int n  = el[ld_row] >> 1;
            int k0 = c*32 + ld_half*16;
            const float* src = (k0 < DHALF) ? posts + (size_t)n*DHALF + k0
                                            : reas  + (size_t)n*DHALF + (k0 - DHALF);
            float4 v0 = ((const float4*)src)[0];
            float4 v1 = ((const float4*)src)[1];
            float4 v2 = ((const float4*)src)[2];
            float4 v3 = ((const float4*)src)[3];
            int kb = ld_half*16;
            sh.m.Xs[kb+ 0][ld_row]=v0.x; sh.m.Xs[kb+ 1][ld_row]=v0.y;
            sh.m.Xs[kb+ 2][ld_row]=v0.z; sh.m.Xs[kb+ 3][ld_row]=v0.w;
            sh.m.Xs[kb+ 4][ld_row]=v1.x; sh.m.Xs[kb+ 5][ld_row]=v1.y;
            sh.m.Xs[kb+ 6][ld_row]=v1.z; sh.m.Xs[kb+ 7][ld_row]=v1.w;
            sh.m.Xs[kb+ 8][ld_row]=v2.x; sh.m.Xs[kb+ 9][ld_row]=v2.y;
            sh.m.Xs[kb+10][ld_row]=v2.z; sh.m.Xs[kb+11][ld_row]=v2.w;
            sh.m.Xs[kb+12][ld_row]=v3.x; sh.m.Xs[kb+13][ld_row]=v3.y;
            sh.m.Xs[kb+14][ld_row]=v3.z; sh.m.Xs[kb+15][ld_row]=v3.w;
        }
        // ---- load W chunk: Ws[k][h] = Uw[r][32c+k][h] ----
        {
            int f = t * 8;                       // 2048 floats / 256 thr
            int k = f >> 6, h = f & 63;
            const float4* src = (const float4*)&UwR[(size_t)(c*32 + k)*HSZ + h];
            float4* dst = (float4*)&sh.m.Ws[k][h];
            dst[0] = src[0]; dst[1] = src[1];
        }
        __syncthreads();
        // ---- FFMA mainloop ----
        #pragma unroll 4
        for (int k = 0; k < 32; k++) {
            float4 a = *(const float4*)&sh.m.Xs[k][4*lane];
            float4 b0 = *(const float4*)&sh.m.Ws[k][8*w];
            float4 b1 = *(const float4*)&sh.m.Ws[k][8*w + 4];
            float av[4] = {a.x, a.y, a.z, a.w};
            float bv[8] = {b0.x,b0.y,b0.z,b0.w,b1.x,b1.y,b1.z,b1.w};
            #pragma unroll
            for (int i = 0; i < 4; i++)
                #pragma unroll
                for (int j = 0; j < 8; j++)
                    acc[i][j] += av[i] * bv[j];
        }
        __syncthreads();
    }

    // ---- add bias, row L2 norm ----
    #pragma unroll
    for (int j = 0; j < 8; j++) {
        float b = Ub[r*HSZ + 8*w + j];
        #pragma unroll
        for (int i = 0; i < 4; i++) acc[i][j] += b;
    }
    #pragma unroll
    for (int i = 0; i < 4; i++) {
        float p = 0.f;
        #pragma unroll
        for (int j = 0; j < 8; j++) p += acc[i][j]*acc[i][j];
        pm[w][4*lane + i] = p;
    }
    __syncthreads();
    if (t < 128) {
        float s = 0.f;
        #pragma unroll
        for (int wi = 0; wi < 8; wi++) s += pm[wi][t];
        rn[t] = 1.f / fmaxf(sqrtf(s), 1e-12f);
    }
    __syncthreads();
    // ---- scale + store normalized rows transposed: Ust[h][row] ----
    #pragma unroll
    for (int i = 0; i < 4; i++) {
        float sc = rn[4*lane + i];
        #pragma unroll
        for (int j = 0; j < 8; j++) acc[i][j] *= sc;
    }
    __syncthreads();   // everyone done reading rn; union about to be repurposed
    #pragma unroll
    for (int j = 0; j < 8; j++) {
        float4 v = make_float4(acc[0][j], acc[1][j], acc[2][j], acc[3][j]);
        *(float4*)&sh.e.Ust[8*w + j][4*lane] = v;
    }
    __syncthreads();

    // ---- score GEMM: acc2[row][l] = sum_h Ust[h][row] * Vlt[r][h][l] ----
    float acc2[4][8];
    #pragma unroll
    for (int i = 0; i < 4; i++)
        #pragma unroll
        for (int j = 0; j < 8; j++) acc2[i][j] = 0.f;

    for (int hc = 0; hc < 2; hc++) {
        {
            int f = t * 8;
            int k = f >> 6, l = f & 63;
            const float4* src = (const float4*)&g_Vlt[(size_t)(r*HSZ + hc*32 + k)*LSZ + l];
            float4* dst = (float4*)&sh.e.Vs[k][l];
            dst[0] = src[0]; dst[1] = src[1];
        }
        __syncthreads();
        #pragma unroll 4
        for (int k = 0; k < 32; k++) {
            float4 a = *(const float4*)&sh.e.Ust[hc*32 + k][4*lane];
            float4 b0 = *(const float4*)&sh.e.Vs[k][8*w];
            float4 b1 = *(const float4*)&sh.e.Vs[k][8*w + 4];
            float av[4] = {a.x, a.y, a.z, a.w};
            float bv[8] = {b0.x,b0.y,b0.z,b0.w,b1.x,b1.y,b1.z,b1.w};
            #pragma unroll
            for (int i = 0; i < 4; i++)
                #pragma unroll
                for (int j = 0; j < 8; j++)
                    acc2[i][j] += av[i] * bv[j];
        }
        __syncthreads();
    }

    // ---- row softmax over 64 cols ----
    #pragma unroll
    for (int i = 0; i < 4; i++) {
        float m = acc2[i][0];
        #pragma unroll
        for (int j = 1; j < 8; j++) m = fmaxf(m, acc2[i][j]);
        pm[w][4*lane + i] = m;
    }
    __syncthreads();
    if (t < 128) {
        float m = pm[0][t];
        #pragma unroll
        for (int wi = 1; wi < 8; wi++) m = fmaxf(m, pm[wi][t]);
        mx[t] = m;
    }
    __syncthreads();
    #pragma unroll
    for (int i = 0; i < 4; i++) {
        float m = mx[4*lane + i], p = 0.f;
        #pragma unroll
        for (int j = 0; j < 8; j++) { acc2[i][j] = expf(acc2[i][j] - m); p += acc2[i][j]; }
        pm[w][4*lane + i] = p;
    }
    __syncthreads();
    if (t < 128) {
        float s = 0.f;
        #pragma unroll
        for (int wi = 0; wi < 8; wi++) s += pm[wi][t];
        rn[t] = 1.f / s;
    }
    __syncthreads();

    // ---- gate-scaled write ----
    #pragma unroll
    for (int i = 0; i < 4; i++) {
        int row = 4*lane + i;
        if (base + row < cnt) {
            float sc = rn[row] * gwv[row];
            int e = el[row];
            float4 o0 = make_float4(acc2[i][0]*sc, acc2[i][1]*sc, acc2[i][2]*sc, acc2[i][3]*sc);
            float4 o1 = make_float4(acc2[i][4]*sc, acc2[i][5]*sc, acc2[i][6]*sc, acc2[i][7]*sc);
            float4* dst = (float4*)&g_out[(size_t)e*LSZ + 8*w];
            dst[0] = o0; dst[1] = o1;
        }
    }
}

// ---------------- sample: combine 2 entries, cumsum, pick, log ----------------
__global__ __launch_bounds__(256) void sample_kernel(const float* __restrict__ rnd,
                                                     float* __restrict__ out_idx,
                                                     float* __restrict__ out_lp) {
    int t = threadIdx.x, lane = t & 31, w = t >> 5;
    int n = blockIdx.x*8 + w;
    const float* b = g_out + (size_t)2*n*LSZ;
    float v0 = b[lane]      + b[64 + lane];
    float v1 = b[32 + lane] + b[96 + lane];
    float rv = rnd[n];
    // inclusive scan of v0
    float s0 = v0;
    #pragma unroll
    for (int o = 1; o < 32; o <<= 1) {
        float u = __shfl_up_sync(0xffffffffu, s0, o);
        if (lane >= o) s0 += u;
    }
    float tot0 = __shfl_sync(0xffffffffu, s0, 31);
    float s1 = v1;
    #pragma unroll
    for (int o = 1; o < 32; o <<= 1) {
        float u = __shfl_up_sync(0xffffffffu, s1, o);
        if (lane >= o) s1 += u;
    }
    s1 += tot0;
    unsigned b0 = __ballot_sync(0xffffffffu, s0 > rv);
    unsigned b1 = __ballot_sync(0xffffffffu, s1 > rv);
    int sel = b0 ? (__ffs(b0) - 1) : (b1 ? (31 + __ffs(b1)) : 0);
    float p = (sel < 32) ? __shfl_sync(0xffffffffu, v0, sel)
                         : __shfl_sync(0xffffffffu, v1, sel - 32);
    if (lane == 0) {
        out_idx[n] = (float)sel;
        out_lp[n]  = logf(p);
    }
}

// ---------------- aux loss ----------------
__global__ void aux_kernel(float* __restrict__ out_aux) {
    float s = 0.f;
    #pragma unroll
    for (int r = 0; r < RSZ; r++)
        s += (g_probsum[r] / (float)NTOK) * ((float)g_cnt[r] / (float)NTOK);
    out_aux[0] = (float)RSZ * s * 0.05f;
}

// ---------------- launch ----------------
extern "C" void kernel_launch(void* const* d_in, const int* in_sizes, int n_in,
                              void* d_out, int out_size) {
    const float* posts = (const float*)d_in[0];
    const float* reas  = (const float*)d_in[1];
    const float* llm   = (const float*)d_in[2];
    const float* rnd   = (const float*)d_in[3];
    const float* gw    = (const float*)d_in[4];
    const float* gb    = (const float*)d_in[5];
    const float* Uw    = (const float*)d_in[6];
    const float* Ub    = (const float*)d_in[7];
    const float* Vw    = (const float*)d_in[8];
    const float* Vb    = (const float*)d_in[9];
    float* out = (float*)d_out;

    init_kernel<<<1, 32>>>();
    vl_kernel<<<dim3(LSZ, RSZ), 64>>>(llm, Vw, Vb);
    gate_kernel<<<NTOK/16, 256>>>(posts, reas, gw, gb);
    proj_kernel<<<dim3(NTOK/128, RSZ), 256>>>(posts, reas, Uw, Ub);
    sample_kernel<<<NTOK/8, 256>>>(rnd, out, out + NTOK);
    aux_kernel<<<1, 1>>>(out + 2*NTOK);
}

// round 3
// speedup vs baseline: 1.0066x; 1.0066x over previous
#include <cuda_runtime.h>
#include <math.h>
#include <stdint.h>

#define NTOK  65536
#define DHALF 384
#define DFULL 768
#define LSZ   64
#define HSZ   64
#define RSZ   8
#define UPAD  65

// ---------------- device scratch (static; no allocations) ----------------
__device__ float g_Vlt[RSZ*HSZ*LSZ];            // normalized V-proj, [r][h][l]
__device__ int   g_cnt[RSZ];
__device__ float g_probsum[RSZ];
__device__ int   g_list[RSZ*NTOK];              // entry e = 2*n + slot
__device__ float g_gate[2*NTOK];                // gate weight per entry
__device__ float g_out[(size_t)2*NTOK*LSZ];     // gate-scaled softmax scores per entry

// ---------------- init ----------------
__global__ void init_kernel() {
    int t = threadIdx.x;
    if (t < RSZ) { g_cnt[t] = 0; g_probsum[t] = 0.f; }
}

// ---------------- Vl = l2norm(llm @ V_w[r] + V_b[r]); store transposed [r][h][l] ------
__global__ __launch_bounds__(64) void vl_kernel(const float* __restrict__ llm,
                                                const float* __restrict__ Vw,
                                                const float* __restrict__ Vb) {
    int l = blockIdx.x, r = blockIdx.y, h = threadIdx.x;
    __shared__ float lsm[DHALF];
    __shared__ float red[64];
    __shared__ float s_inv;
    for (int i = h; i < DHALF; i += 64) lsm[i] = llm[l*DHALF + i];
    __syncthreads();
    float acc = Vb[r*HSZ + h];
    const float* w = Vw + ((size_t)r*DHALF)*HSZ + h;
    #pragma unroll 8
    for (int d = 0; d < DHALF; d++) acc += lsm[d] * w[(size_t)d*HSZ];
    red[h] = acc*acc;
    __syncthreads();
    if (h == 0) {
        float ss = 0.f;
        #pragma unroll
        for (int i = 0; i < 64; i++) ss += red[i];
        s_inv = 1.f / fmaxf(sqrtf(ss), 1e-12f);
    }
    __syncthreads();
    g_Vlt[(r*HSZ + h)*LSZ + l] = acc * s_inv;
}

// ---------------- gate: logits, softmax, top-2, aggregated list build ----------------
#define GTOK 64
__global__ __launch_bounds__(256) void gate_kernel(const float* __restrict__ posts,
                                                   const float* __restrict__ reas,
                                                   const float* __restrict__ gw,
                                                   const float* __restrict__ gb) {
    __shared__ float wsm[RSZ*DFULL];   // [r][k]
    __shared__ float pblk[8][RSZ];
    __shared__ int   i1s[GTOK], i2s[GTOK];
    __shared__ int   locs[2*GTOK];
    __shared__ int   bases[RSZ];
    int t = threadIdx.x, lane = t & 31, w = t >> 5;
    for (int idx = t; idx < RSZ*DFULL; idx += 256) {
        int k = idx >> 3, r = idx & 7;
        wsm[r*DFULL + k] = gw[idx];
    }
    if (lane < RSZ) pblk[w][lane] = 0.f;
    __syncthreads();

    int nblk = blockIdx.x * GTOK;
    for (int tok = 0; tok < 8; tok++) {
        int tl = w*8 + tok;
        int n  = nblk + tl;
        float acc[RSZ];
        #pragma unroll
        for (int r = 0; r < RSZ; r++) acc[r] = 0.f;
        const float* xp = posts + (size_t)n*DHALF;
        const float* xq = reas  + (size_t)n*DHALF;
        #pragma unroll
        for (int i = 0; i < 3; i++) {
            int k = 4*lane + 128*i;
            float4 xv = *(const float4*)(xp + k);
            #pragma unroll
            for (int r = 0; r < RSZ; r++) {
                float4 wv = *(const float4*)&wsm[r*DFULL + k];
                acc[r] += xv.x*wv.x + xv.y*wv.y + xv.z*wv.z + xv.w*wv.w;
            }
        }
        #pragma unroll
        for (int i = 0; i < 3; i++) {
            int k = 4*lane + 128*i;
            float4 xv = *(const float4*)(xq + k);
            #pragma unroll
            for (int r = 0; r < RSZ; r++) {
                float4 wv = *(const float4*)&wsm[r*DFULL + DHALF + k];
                acc[r] += xv.x*wv.x + xv.y*wv.y + xv.z*wv.z + xv.w*wv.w;
            }
        }
        #pragma unroll
        for (int r = 0; r < RSZ; r++) {
            #pragma unroll
            for (int o = 16; o > 0; o >>= 1)
                acc[r] += __shfl_xor_sync(0xffffffffu, acc[r], o);
        }
        if (lane == 0) {
            float lg[RSZ];
            #pragma unroll
            for (int r = 0; r < RSZ; r++) lg[r] = acc[r] + gb[r];
            float v1 = -1e30f, v2 = -1e30f; int i1 = 0, i2 = 0;
            #pragma unroll
            for (int r = 0; r < RSZ; r++) {
                if (lg[r] > v1)      { v2 = v1; i2 = i1; v1 = lg[r]; i1 = r; }
                else if (lg[r] > v2) { v2 = lg[r]; i2 = r; }
            }
            float s = 0.f, p[RSZ];
            #pragma unroll
            for (int r = 0; r < RSZ; r++) { p[r] = expf(lg[r] - v1); s += p[r]; }
            float invs = 1.f / s;
            #pragma unroll
            for (int r = 0; r < RSZ; r++) pblk[w][r] += p[r]*invs;
            float g0 = 1.f / (1.f + expf(v2 - v1));
            g_gate[2*n]   = g0;
            g_gate[2*n+1] = 1.f - g0;
            i1s[tl] = i1; i2s[tl] = i2;
        }
    }
    __syncthreads();
    // per-router compaction (8 serial scanners), 8 atomics per block total
    if (t < RSZ) {
        int c = 0;
        for (int e = 0; e < 2*GTOK; e++) {
            int rid = (e & 1) ? i2s[e >> 1] : i1s[e >> 1];
            if (rid == t) locs[e] = c++;
        }
        bases[t] = atomicAdd(&g_cnt[t], c);
    }
    __syncthreads();
    if (t < 2*GTOK) {
        int rid = (t & 1) ? i2s[t >> 1] : i1s[t >> 1];
        g_list[rid*NTOK + bases[rid] + locs[t]] = 2*(nblk + (t >> 1)) + (t & 1);
    }
    if (t < RSZ) {
        float s = 0.f;
        #pragma unroll
        for (int wi = 0; wi < 8; wi++) s += pblk[wi][t];
        atomicAdd(&g_probsum[t], s);
    }
}

// ---------------- proj: gathered GEMM (FFMA2) + norm + score GEMM + softmax ----------
struct ProjSmem {
    union {
        struct { float Xs[2][32][128]; float Ws[2][32][64]; } m;
        struct { float Ust[128][UPAD]; float Vs[64][64]; } e;
    } u;
    float pm[4][128];
    float rn[128];
    float mx[128];
    int   el[128];
    float gwv[128];
};

__device__ __forceinline__ void cp16(uint32_t dst, const void* src) {
    asm volatile("cp.async.ca.shared.global [%0], [%1], 16;" :: "r"(dst), "l"(src));
}

__global__ __launch_bounds__(256) void proj_kernel(const float* __restrict__ posts,
                                                   const float* __restrict__ reas,
                                                   const float* __restrict__ Uw,
                                                   const float* __restrict__ Ub) {
    int r = blockIdx.y;
    int cnt = g_cnt[r];
    int base = blockIdx.x * 128;
    if (base >= cnt) return;

    extern __shared__ char smraw[];
    ProjSmem& sh = *reinterpret_cast<ProjSmem*>(smraw);

    int t = threadIdx.x, lane = t & 31, w = t >> 5;
    int rgrp = w >> 2, cgrp = w & 3;
    int row0 = rgrp*64 + lane;            // second row = row0 + 32
    int bcol = cgrp*16;
    int ld_row = t & 127, ld_half = t >> 7;

    if (t < 128) {
        int i = base + t;
        int e = (i < cnt) ? g_list[r*NTOK + i] : g_list[r*NTOK + base];
        sh.el[t] = e;
        sh.gwv[t] = g_gate[e];
    }
    __syncthreads();

    const float* UwR = Uw + (size_t)r*DFULL*HSZ;
    float4 xr4[4];

    auto ldx = [&](int c) {
        int n  = sh.el[ld_row] >> 1;
        int k0 = c*32 + ld_half*16;
        const float* src = (k0 < DHALF) ? posts + (size_t)n*DHALF + k0
                                        : reas  + (size_t)n*DHALF + (k0 - DHALF);
        xr4[0] = ((const float4*)src)[0];
        xr4[1] = ((const float4*)src)[1];
        xr4[2] = ((const float4*)src)[2];
        xr4[3] = ((const float4*)src)[3];
    };
    auto stx = [&](int buf) {
        int kb = ld_half*16;
        float* X = &sh.u.m.Xs[buf][0][0];
        #pragma unroll
        for (int q = 0; q < 4; q++) {
            float4 v = xr4[q];
            X[(kb + 4*q + 0)*128 + ld_row] = v.x;
            X[(kb + 4*q + 1)*128 + ld_row] = v.y;
            X[(kb + 4*q + 2)*128 + ld_row] = v.z;
            X[(kb + 4*q + 3)*128 + ld_row] = v.w;
        }
    };
    auto ldw = [&](int c, int buf) {
        const float4* src = (const float4*)(UwR + (size_t)c*2048) + t*2;
        uint32_t dst = (uint32_t)__cvta_generic_to_shared(&sh.u.m.Ws[buf][0][0]) + t*32;
        cp16(dst, src);
        cp16(dst + 16, src + 1);
        asm volatile("cp.async.commit_group;" ::: "memory");
    };

    unsigned long long acc[2][8];
    #pragma unroll
    for (int i = 0; i < 2; i++)
        #pragma unroll
        for (int j = 0; j < 8; j++) acc[i][j] = 0ull;

    auto comp = [&](int buf) {
        #pragma unroll 8
        for (int k = 0; k < 32; k++) {
            float a0 = sh.u.m.Xs[buf][k][row0];
            float a1 = sh.u.m.Xs[buf][k][row0 + 32];
            unsigned long long A0, A1;
            asm("mov.b64 %0, {%1, %1};" : "=l"(A0) : "f"(a0));
            asm("mov.b64 %0, {%1, %1};" : "=l"(A1) : "f"(a1));
            #pragma unroll
            for (int j = 0; j < 4; j++) {
                ulonglong2 bb = *(const ulonglong2*)&sh.u.m.Ws[buf][k][bcol + 4*j];
                asm("fma.rn.f32x2 %0, %1, %2, %0;" : "+l"(acc[0][2*j  ]) : "l"(A0), "l"(bb.x));
                asm("fma.rn.f32x2 %0, %1, %2, %0;" : "+l"(acc[0][2*j+1]) : "l"(A0), "l"(bb.y));
                asm("fma.rn.f32x2 %0, %1, %2, %0;" : "+l"(acc[1][2*j  ]) : "l"(A1), "l"(bb.x));
                asm("fma.rn.f32x2 %0, %1, %2, %0;" : "+l"(acc[1][2*j+1]) : "l"(A1), "l"(bb.y));
            }
        }
    };

    // prologue: fill stage 0, start stage 1
    ldx(0); ldw(0, 0); stx(0);
    ldx(1); ldw(1, 1);
    asm volatile("cp.async.wait_group 1;" ::: "memory");
    __syncthreads();

    for (int c = 0; c < 24; c++) {
        comp(c & 1);
        if (c + 1 < 24) {
            stx((c + 1) & 1);
            asm volatile("cp.async.wait_group 0;" ::: "memory");
        }
        __syncthreads();
        if (c + 2 < 24) { ldx(c + 2); ldw(c + 2, c & 1); }
    }

    // ---- unpack, bias, row L2 norm partials ----
    float cv[2][16];
    #pragma unroll
    for (int i = 0; i < 2; i++)
        #pragma unroll
        for (int j = 0; j < 8; j++) {
            unsigned long long v = acc[i][j];
            cv[i][2*j]   = __uint_as_float((unsigned)(v & 0xffffffffull));
            cv[i][2*j+1] = __uint_as_float((unsigned)(v >> 32));
        }
    #pragma unroll
    for (int col = 0; col < 16; col++) {
        float b = Ub[r*HSZ + bcol + col];
        cv[0][col] += b; cv[1][col] += b;
    }
    #pragma unroll
    for (int i = 0; i < 2; i++) {
        float p = 0.f;
        #pragma unroll
        for (int col = 0; col < 16; col++) p += cv[i][col]*cv[i][col];
        sh.pm[cgrp][row0 + 32*i] = p;
    }
    // cooperative Vs load (overlays mainloop W area; mainloop done)
    {
        const float4* src = (const float4*)(g_Vlt + (size_t)r*HSZ*LSZ) + t*4;
        float4* dst = (float4*)&sh.u.e.Vs[0][0] + t*4;
        #pragma unroll
        for (int q = 0; q < 4; q++) dst[q] = src[q];
    }
    __syncthreads();
    if (t < 128) {
        float s = sh.pm[0][t] + sh.pm[1][t] + sh.pm[2][t] + sh.pm[3][t];
        sh.rn[t] = 1.f / fmaxf(sqrtf(s), 1e-12f);
    }
    __syncthreads();
    {
        float s0 = sh.rn[row0], s1 = sh.rn[row0 + 32];
        #pragma unroll
        for (int col = 0; col < 16; col++) { cv[0][col] *= s0; cv[1][col] *= s1; }
    }
    #pragma unroll
    for (int col = 0; col < 16; col++) {
        sh.u.e.Ust[row0][bcol + col]      = cv[0][col];
        sh.u.e.Ust[row0 + 32][bcol + col] = cv[1][col];
    }
    __syncthreads();

    // ---- score GEMM: acc2[row][l] = sum_h Ust[row][h] * Vs[h][l] ----
    unsigned long long acc2[2][8];
    #pragma unroll
    for (int i = 0; i < 2; i++)
        #pragma unroll
        for (int j = 0; j < 8; j++) acc2[i][j] = 0ull;
    #pragma unroll 8
    for (int k = 0; k < 64; k++) {
        float a0 = sh.u.e.Ust[row0][k];
        float a1 = sh.u.e.Ust[row0 + 32][k];
        unsigned long long A0, A1;
        asm("mov.b64 %0, {%1, %1};" : "=l"(A0) : "f"(a0));
        asm("mov.b64 %0, {%1, %1};" : "=l"(A1) : "f"(a1));
        #pragma unroll
        for (int j = 0; j < 4; j++) {
            ulonglong2 bb = *(const ulonglong2*)&sh.u.e.Vs[k][bcol + 4*j];
            asm("fma.rn.f32x2 %0, %1, %2, %0;" : "+l"(acc2[0][2*j  ]) : "l"(A0), "l"(bb.x));
            asm("fma.rn.f32x2 %0, %1, %2, %0;" : "+l"(acc2[0][2*j+1]) : "l"(A0), "l"(bb.y));
            asm("fma.rn.f32x2 %0, %1, %2, %0;" : "+l"(acc2[1][2*j  ]) : "l"(A1), "l"(bb.x));
            asm("fma.rn.f32x2 %0, %1, %2, %0;" : "+l"(acc2[1][2*j+1]) : "l"(A1), "l"(bb.y));
        }
    }
    float cw[2][16];
    #pragma unroll
    for (int i = 0; i < 2; i++)
        #pragma unroll
        for (int j = 0; j < 8; j++) {
            unsigned long long v = acc2[i][j];
            cw[i][2*j]   = __uint_as_float((unsigned)(v & 0xffffffffull));
            cw[i][2*j+1] = __uint_as_float((unsigned)(v >> 32));
        }

    // ---- row softmax over 64 cols ----
    #pragma unroll
    for (int i = 0; i < 2; i++) {
        float m = cw[i][0];
        #pragma unroll
        for (int col = 1; col < 16; col++) m = fmaxf(m, cw[i][col]);
        sh.pm[cgrp][row0 + 32*i] = m;
    }
    __syncthreads();
    if (t < 128) {
        float m = fmaxf(fmaxf(sh.pm[0][t], sh.pm[1][t]), fmaxf(sh.pm[2][t], sh.pm[3][t]));
        sh.mx[t] = m;
    }
    __syncthreads();
    #pragma unroll
    for (int i = 0; i < 2; i++) {
        float m = sh.mx[row0 + 32*i], p = 0.f;
        #pragma unroll
        for (int col = 0; col < 16; col++) { cw[i][col] = expf(cw[i][col] - m); p += cw[i][col]; }
        sh.pm[cgrp][row0 + 32*i] = p;
    }
    __syncthreads();
    if (t < 128) {
        float s = sh.pm[0][t] + sh.pm[1][t] + sh.pm[2][t] + sh.pm[3][t];
        sh.rn[t] = 1.f / s;
    }
    __syncthreads();

    // ---- gate-scaled write ----
    #pragma unroll
    for (int i = 0; i < 2; i++) {
        int row = row0 + 32*i;
        if (base + row < cnt) {
            float sc = sh.rn[row] * sh.gwv[row];
            int e = sh.el[row];
            float* dst = g_out + (size_t)e*LSZ + bcol;
            #pragma unroll
            for (int q = 0; q < 4; q++) {
                float4 o = make_float4(cw[i][4*q]*sc, cw[i][4*q+1]*sc,
                                       cw[i][4*q+2]*sc, cw[i][4*q+3]*sc);
                ((float4*)dst)[q] = o;
            }
        }
    }
}

// ---------------- sample: combine 2 entries, cumsum, pick, log ----------------
__global__ __launch_bounds__(256) void sample_kernel(const float* __restrict__ rnd,
                                                     float* __restrict__ out_idx,
                                                     float* __restrict__ out_lp) {
    int t = threadIdx.x, lane = t & 31, w = t >> 5;
    int n = blockIdx.x*8 + w;
    const float* b = g_out + (size_t)2*n*LSZ;
    float v0 = b[lane]      + b[64 + lane];
    float v1 = b[32 + lane] + b[96 + lane];
    float rv = rnd[n];
    float s0 = v0;
    #pragma unroll
    for (int o = 1; o < 32; o <<= 1) {
        float u = __shfl_up_sync(0xffffffffu, s0, o);
        if (lane >= o) s0 += u;
    }
    float tot0 = __shfl_sync(0xffffffffu, s0, 31);
    float s1 = v1;
    #pragma unroll
    for (int o = 1; o < 32; o <<= 1) {
        float u = __shfl_up_sync(0xffffffffu, s1, o);
        if (lane >= o) s1 += u;
    }
    s1 += tot0;
    unsigned b0 = __ballot_sync(0xffffffffu, s0 > rv);
    unsigned b1 = __ballot_sync(0xffffffffu, s1 > rv);
    int sel = b0 ? (__ffs(b0) - 1) : (b1 ? (31 + __ffs(b1)) : 0);
    float p = (sel < 32) ? __shfl_sync(0xffffffffu, v0, sel)
                         : __shfl_sync(0xffffffffu, v1, sel - 32);
    if (lane == 0) {
        out_idx[n] = (float)sel;
        out_lp[n]  = logf(p);
    }
}

// ---------------- aux loss ----------------
__global__ void aux_kernel(float* __restrict__ out_aux) {
    float s = 0.f;
    #pragma unroll
    for (int r = 0; r < RSZ; r++)
        s += (g_probsum[r] / (float)NTOK) * ((float)g_cnt[r] / (float)NTOK);
    out_aux[0] = (float)RSZ * s * 0.05f;
}

// ---------------- launch ----------------
extern "C" void kernel_launch(void* const* d_in, const int* in_sizes, int n_in,
                              void* d_out, int out_size) {
    const float* posts = (const float*)d_in[0];
    const float* reas  = (const float*)d_in[1];
    const float* llm   = (const float*)d_in[2];
    const float* rnd   = (const float*)d_in[3];
    const float* gw    = (const float*)d_in[4];
    const float* gb    = (const float*)d_in[5];
    const float* Uw    = (const float*)d_in[6];
    const float* Ub    = (const float*)d_in[7];
    const float* Vw    = (const float*)d_in[8];
    const float* Vb    = (const float*)d_in[9];
    float* out = (float*)d_out;

    static bool attr_done = false;
    if (!attr_done) {
        cudaFuncSetAttribute(proj_kernel, cudaFuncAttributeMaxDynamicSharedMemorySize,
                             (int)sizeof(ProjSmem));
        attr_done = true;
    }

    init_kernel<<<1, 32>>>();
    vl_kernel<<<dim3(LSZ, RSZ), 64>>>(llm, Vw, Vb);
    gate_kernel<<<NTOK/GTOK, 256>>>(posts, reas, gw, gb);
    proj_kernel<<<dim3(NTOK/128, RSZ), 256, sizeof(ProjSmem)>>>(posts, reas, Uw, Ub);
    sample_kernel<<<NTOK/8, 256>>>(rnd, out, out + NTOK);
    aux_kernel<<<1, 1>>>(out + 2*NTOK);
}

// round 4
// speedup vs baseline: 1.0304x; 1.0237x over previous
#include <cuda_runtime.h>
#include <cuda_bf16.h>
#include <math.h>
#include <stdint.h>

#define NTOK  65536
#define DHALF 384
#define DFULL 768
#define LSZ   64
#define HSZ   64
#define RSZ   8

// ---------------- device scratch (static; no allocations) ----------------
__device__ int   g_cnt[RSZ];
__device__ float g_probsum[RSZ];
__device__ int   g_list[RSZ*NTOK];              // entry e = 2*n + slot
__device__ float g_gate[2*NTOK];                // gate weight per entry
__device__ float g_out[(size_t)2*NTOK*LSZ];     // gate-scaled softmax scores per entry
// pre-split, pre-swizzled Vl (ldmatrix layout, [r] blocks of 64 rows x 128B)
__device__ __align__(16) char g_VhSwz[RSZ*8192];
__device__ __align__(16) char g_VlSwz[RSZ*8192];

// ---------------- helpers ----------------
__device__ __forceinline__ uint32_t packbf(float lo, float hi) {
    uint32_t d;
    asm("cvt.rn.bf16x2.f32 %0, %1, %2;" : "=r"(d) : "f"(hi), "f"(lo));
    return d;
}
__device__ __forceinline__ void split2(float x0, float x1, uint32_t& hp, uint32_t& lp) {
    hp = packbf(x0, x1);
    float h0 = __uint_as_float(hp << 16);
    float h1 = __uint_as_float(hp & 0xffff0000u);
    lp = packbf(x0 - h0, x1 - h1);
}
__device__ __forceinline__ void ldsm4(uint32_t r[4], uint32_t addr) {
    asm volatile("ldmatrix.sync.aligned.m8n8.x4.shared.b16 {%0,%1,%2,%3}, [%4];"
        : "=r"(r[0]), "=r"(r[1]), "=r"(r[2]), "=r"(r[3]) : "r"(addr));
}
__device__ __forceinline__ void ldsm4t(uint32_t r[4], uint32_t addr) {
    asm volatile("ldmatrix.sync.aligned.m8n8.x4.trans.shared.b16 {%0,%1,%2,%3}, [%4];"
        : "=r"(r[0]), "=r"(r[1]), "=r"(r[2]), "=r"(r[3]) : "r"(addr));
}
__device__ __forceinline__ void mma16816(float c[4], const uint32_t a[4],
                                         uint32_t b0, uint32_t b1) {
    asm volatile("mma.sync.aligned.m16n8k16.row.col.f32.bf16.bf16.f32 "
        "{%0,%1,%2,%3}, {%4,%5,%6,%7}, {%8,%9}, {%0,%1,%2,%3};"
        : "+f"(c[0]), "+f"(c[1]), "+f"(c[2]), "+f"(c[3])
        : "r"(a[0]), "r"(a[1]), "r"(a[2]), "r"(a[3]), "r"(b0), "r"(b1));
}

// ---------------- init ----------------
__global__ void init_kernel() {
    int t = threadIdx.x;
    if (t < RSZ) { g_cnt[t] = 0; g_probsum[t] = 0.f; }
}

// ---------------- Vl = l2norm(llm @ V_w[r] + V_b[r]); emit swizzled bf16 hi/lo -------
__global__ __launch_bounds__(64) void vl_kernel(const float* __restrict__ llm,
                                                const float* __restrict__ Vw,
                                                const float* __restrict__ Vb) {
    int l = blockIdx.x, r = blockIdx.y, h = threadIdx.x;
    __shared__ float lsm[DHALF];
    __shared__ float red[64];
    __shared__ float s_inv;
    for (int i = h; i < DHALF; i += 64) lsm[i] = llm[l*DHALF + i];
    __syncthreads();
    float acc = Vb[r*HSZ + h];
    const float* w = Vw + ((size_t)r*DHALF)*HSZ + h;
    #pragma unroll 8
    for (int d = 0; d < DHALF; d++) acc += lsm[d] * w[(size_t)d*HSZ];
    red[h] = acc*acc;
    __syncthreads();
    if (h == 0) {
        float ss = 0.f;
        #pragma unroll
        for (int i = 0; i < 64; i++) ss += red[i];
        s_inv = 1.f / fmaxf(sqrtf(ss), 1e-12f);
    }
    __syncthreads();
    float val = acc * s_inv;
    __nv_bfloat16 hb = __float2bfloat16(val);
    unsigned short hbits = __bfloat16_as_ushort(hb);
    float hf = __uint_as_float(((uint32_t)hbits) << 16);
    unsigned short lbits = __bfloat16_as_ushort(__float2bfloat16(val - hf));
    // V smem layout: row = h (128B of 64 l-values bf16), swizzled at 16B grain
    uint32_t off = (uint32_t)(h*128 + l*2) ^ ((uint32_t)(h & 7) << 4);
    *(unsigned short*)(g_VhSwz + r*8192 + off) = hbits;
    *(unsigned short*)(g_VlSwz + r*8192 + off) = lbits;
}

// ---------------- gate: logits, softmax, top-2, aggregated list build ----------------
#define GTOK 64
__global__ __launch_bounds__(256) void gate_kernel(const float* __restrict__ posts,
                                                   const float* __restrict__ reas,
                                                   const float* __restrict__ gw,
                                                   const float* __restrict__ gb) {
    __shared__ float wsm[RSZ*DFULL];   // [r][k]
    __shared__ float pblk[8][RSZ];
    __shared__ int   i1s[GTOK], i2s[GTOK];
    __shared__ int   locs[2*GTOK];
    __shared__ int   bases[RSZ];
    int t = threadIdx.x, lane = t & 31, w = t >> 5;
    for (int idx = t; idx < RSZ*DFULL; idx += 256) {
        int k = idx >> 3, r = idx & 7;
        wsm[r*DFULL + k] = gw[idx];
    }
    if (lane < RSZ) pblk[w][lane] = 0.f;
    __syncthreads();

    int nblk = blockIdx.x * GTOK;
    for (int tok = 0; tok < 8; tok++) {
        int tl = w*8 + tok;
        int n  = nblk + tl;
        float acc[RSZ];
        #pragma unroll
        for (int r = 0; r < RSZ; r++) acc[r] = 0.f;
        const float* xp = posts + (size_t)n*DHALF;
        const float* xq = reas  + (size_t)n*DHALF;
        #pragma unroll
        for (int i = 0; i < 3; i++) {
            int k = 4*lane + 128*i;
            float4 xv = *(const float4*)(xp + k);
            #pragma unroll
            for (int r = 0; r < RSZ; r++) {
                float4 wv = *(const float4*)&wsm[r*DFULL + k];
                acc[r] += xv.x*wv.x + xv.y*wv.y + xv.z*wv.z + xv.w*wv.w;
            }
        }
        #pragma unroll
        for (int i = 0; i < 3; i++) {
            int k = 4*lane + 128*i;
            float4 xv = *(const float4*)(xq + k);
            #pragma unroll
            for (int r = 0; r < RSZ; r++) {
                float4 wv = *(const float4*)&wsm[r*DFULL + DHALF + k];
                acc[r] += xv.x*wv.x + xv.y*wv.y + xv.z*wv.z + xv.w*wv.w;
            }
        }
        #pragma unroll
        for (int r = 0; r < RSZ; r++) {
            #pragma unroll
            for (int o = 16; o > 0; o >>= 1)
                acc[r] += __shfl_xor_sync(0xffffffffu, acc[r], o);
        }
        if (lane == 0) {
            float lg[RSZ];
            #pragma unroll
            for (int r = 0; r < RSZ; r++) lg[r] = acc[r] + gb[r];
            float v1 = -1e30f, v2 = -1e30f; int i1 = 0, i2 = 0;
            #pragma unroll
            for (int r = 0; r < RSZ; r++) {
                if (lg[r] > v1)      { v2 = v1; i2 = i1; v1 = lg[r]; i1 = r; }
                else if (lg[r] > v2) { v2 = lg[r]; i2 = r; }
            }
            float s = 0.f, p[RSZ];
            #pragma unroll
            for (int r = 0; r < RSZ; r++) { p[r] = expf(lg[r] - v1); s += p[r]; }
            float invs = 1.f / s;
            #pragma unroll
            for (int r = 0; r < RSZ; r++) pblk[w][r] += p[r]*invs;
            float g0 = 1.f / (1.f + expf(v2 - v1));
            g_gate[2*n]   = g0;
            g_gate[2*n+1] = 1.f - g0;
            i1s[tl] = i1; i2s[tl] = i2;
        }
    }
    __syncthreads();
    if (t < RSZ) {
        int c = 0;
        for (int e = 0; e < 2*GTOK; e++) {
            int rid = (e & 1) ? i2s[e >> 1] : i1s[e >> 1];
            if (rid == t) locs[e] = c++;
        }
        bases[t] = atomicAdd(&g_cnt[t], c);
    }
    __syncthreads();
    if (t < 2*GTOK) {
        int rid = (t & 1) ? i2s[t >> 1] : i1s[t >> 1];
        g_list[rid*NTOK + bases[rid] + locs[t]] = 2*(nblk + (t >> 1)) + (t & 1);
    }
    if (t < RSZ) {
        float s = 0.f;
        #pragma unroll
        for (int wi = 0; wi < 8; wi++) s += pblk[wi][t];
        atomicAdd(&g_probsum[t], s);
    }
}

// ---------------- proj: bf16x3 tensor-core gathered GEMM + fused epilogue ----------
struct ProjSmem {
    union {
        struct { char Ah[128*128]; char Al[128*128]; char Wh[64*128]; char Wl[64*128]; } m;
        struct { char Uh[128*128]; char Ul[128*128]; char Vh[64*128]; char Vl[64*128]; } e;
    } u;                                    // 48 KB, both phases same layout
    int   el[128];
    float gwv[128];
    float bs[64];
};

__global__ __launch_bounds__(256, 2) void proj_kernel(const float* __restrict__ posts,
                                                      const float* __restrict__ reas,
                                                      const float* __restrict__ Uw,
                                                      const float* __restrict__ Ub) {
    int r = blockIdx.y;
    int cnt = g_cnt[r];
    int base = blockIdx.x * 128;
    if (base >= cnt) return;

    extern __shared__ char smraw[];
    ProjSmem& sh = *reinterpret_cast<ProjSmem*>(smraw);

    int t = threadIdx.x, lane = t & 31, w = t >> 5;
    const int R0 = 16*w;
    const int g  = lane >> 2;      // row group within warp tile
    const int tq = lane & 3;       // col quad

    if (t < 128) {
        int i = base + t;
        int e = (i < cnt) ? g_list[r*NTOK + i] : g_list[r*NTOK + base];
        sh.el[t] = e;
        sh.gwv[t] = g_gate[e];
    }
    if (t < 64) sh.bs[t] = Ub[r*HSZ + t];
    __syncthreads();

    const float* UwR = Uw + (size_t)r*DFULL*HSZ;

    uint32_t AhB = (uint32_t)__cvta_generic_to_shared(sh.u.m.Ah);
    uint32_t AlB = (uint32_t)__cvta_generic_to_shared(sh.u.m.Al);
    uint32_t WhB = (uint32_t)__cvta_generic_to_shared(sh.u.m.Wh);
    uint32_t WlB = (uint32_t)__cvta_generic_to_shared(sh.u.m.Wl);

    // staging roles
    int srow = t >> 1, shalf = t & 1;       // X: 128 rows, 2 half-rows of 32 floats
    int wrow = t >> 2, wq = t & 3;          // W: 64 rows, 4 quarters of 16 floats
    int xn_row = sh.el[srow] >> 1;

    float acc[8][4];
    #pragma unroll
    for (int j = 0; j < 8; j++)
        #pragma unroll
        for (int q = 0; q < 4; q++) acc[j][q] = 0.f;

    for (int c = 0; c < 12; c++) {
        // ---- stage X chunk (gathered rows, fp32 -> bf16 hi/lo, swizzled) ----
        {
            const float* src = ((c < 6) ? posts + (size_t)xn_row*DHALF + c*64
                                        : reas  + (size_t)xn_row*DHALF + (c - 6)*64)
                               + shalf*32;
            uint32_t rowbase = srow*128 + shalf*64;
            uint32_t xorv = (uint32_t)(srow & 7) << 4;
            #pragma unroll
            for (int q2 = 0; q2 < 4; q2++) {
                float4 v0 = ((const float4*)src)[2*q2];
                float4 v1 = ((const float4*)src)[2*q2 + 1];
                uint32_t h0,h1,h2,h3,l0,l1,l2,l3;
                split2(v0.x, v0.y, h0, l0); split2(v0.z, v0.w, h1, l1);
                split2(v1.x, v1.y, h2, l2); split2(v1.z, v1.w, h3, l3);
                uint32_t off = (rowbase + q2*16) ^ xorv;
                *(uint4*)(sh.u.m.Ah + off) = make_uint4(h0,h1,h2,h3);
                *(uint4*)(sh.u.m.Al + off) = make_uint4(l0,l1,l2,l3);
            }
        }
        // ---- stage W chunk ----
        {
            const float* src = UwR + ((size_t)(c*64 + wrow))*HSZ + wq*16;
            uint32_t rowbase = wrow*128 + wq*32;
            uint32_t xorv = (uint32_t)(wrow & 7) << 4;
            #pragma unroll
            for (int q2 = 0; q2 < 2; q2++) {
                float4 v0 = ((const float4*)src)[2*q2];
                float4 v1 = ((const float4*)src)[2*q2 + 1];
                uint32_t h0,h1,h2,h3,l0,l1,l2,l3;
                split2(v0.x, v0.y, h0, l0); split2(v0.z, v0.w, h1, l1);
                split2(v1.x, v1.y, h2, l2); split2(v1.z, v1.w, h3, l3);
                uint32_t off = (rowbase + q2*16) ^ xorv;
                *(uint4*)(sh.u.m.Wh + off) = make_uint4(h0,h1,h2,h3);
                *(uint4*)(sh.u.m.Wl + off) = make_uint4(l0,l1,l2,l3);
            }
        }
        __syncthreads();
        // ---- tensor mainloop: 4 k16-steps, bf16x3 ----
        #pragma unroll
        for (int kk = 0; kk < 4; kk++) {
            int arow = R0 + (lane & 15);
            uint32_t aoff = (uint32_t)(arow*128 + (2*kk + (lane >> 4))*16)
                            ^ ((uint32_t)(arow & 7) << 4);
            uint32_t ah[4], al[4];
            ldsm4(ah, AhB + aoff);
            ldsm4(al, AlB + aoff);
            int krow = 16*kk + (lane & 15);
            uint32_t bxor = (uint32_t)(krow & 7) << 4;
            #pragma unroll
            for (int f = 0; f < 4; f++) {
                uint32_t boff = (uint32_t)(krow*128 + (2*f + (lane >> 4))*16) ^ bxor;
                uint32_t bh[4], bl[4];
                ldsm4t(bh, WhB + boff);
                mma16816(acc[2*f],     ah, bh[0], bh[1]);
                mma16816(acc[2*f + 1], ah, bh[2], bh[3]);
                mma16816(acc[2*f],     al, bh[0], bh[1]);
                mma16816(acc[2*f + 1], al, bh[2], bh[3]);
                ldsm4t(bl, WlB + boff);
                mma16816(acc[2*f],     ah, bl[0], bl[1]);
                mma16816(acc[2*f + 1], ah, bl[2], bl[3]);
            }
        }
        __syncthreads();
    }

    // ---- copy pre-swizzled V tiles (overlays W region; mainloop done) ----
    {
        const uint4* srcH = (const uint4*)(g_VhSwz + r*8192);
        const uint4* srcL = (const uint4*)(g_VlSwz + r*8192);
        ((uint4*)sh.u.e.Vh)[t]       = srcH[t];
        ((uint4*)sh.u.e.Vh)[t + 256] = srcH[t + 256];
        ((uint4*)sh.u.e.Vl)[t]       = srcL[t];
        ((uint4*)sh.u.e.Vl)[t + 256] = srcL[t + 256];
    }

    // ---- bias + row L2 norm (warp-local: rows R0+g and R0+g+8) ----
    float s0 = 0.f, s1 = 0.f;
    #pragma unroll
    for (int j = 0; j < 8; j++) {
        float b0 = sh.bs[8*j + 2*tq], b1 = sh.bs[8*j + 2*tq + 1];
        acc[j][0] += b0; acc[j][1] += b1;
        acc[j][2] += b0; acc[j][3] += b1;
        s0 += acc[j][0]*acc[j][0] + acc[j][1]*acc[j][1];
        s1 += acc[j][2]*acc[j][2] + acc[j][3]*acc[j][3];
    }
    s0 += __shfl_xor_sync(0xffffffffu, s0, 1);
    s0 += __shfl_xor_sync(0xffffffffu, s0, 2);
    s1 += __shfl_xor_sync(0xffffffffu, s1, 1);
    s1 += __shfl_xor_sync(0xffffffffu, s1, 2);
    float inv0 = 1.f / fmaxf(sqrtf(s0), 1e-12f);
    float inv1 = 1.f / fmaxf(sqrtf(s1), 1e-12f);

    // ---- store normalized rows as bf16 hi/lo into U tiles (A layout) ----
    {
        int rowA = R0 + g, rowB = R0 + g + 8;
        uint32_t xorA = (uint32_t)(rowA & 7) << 4;
        uint32_t xorB = (uint32_t)(rowB & 7) << 4;
        #pragma unroll
        for (int j = 0; j < 8; j++) {
            uint32_t hp, lp;
            split2(acc[j][0]*inv0, acc[j][1]*inv0, hp, lp);
            uint32_t offA = (uint32_t)(rowA*128 + 16*j + 4*tq) ^ xorA;
            *(uint32_t*)(sh.u.e.Uh + offA) = hp;
            *(uint32_t*)(sh.u.e.Ul + offA) = lp;
            split2(acc[j][2]*inv1, acc[j][3]*inv1, hp, lp);
            uint32_t offB = (uint32_t)(rowB*128 + 16*j + 4*tq) ^ xorB;
            *(uint32_t*)(sh.u.e.Uh + offB) = hp;
            *(uint32_t*)(sh.u.e.Ul + offB) = lp;
        }
    }
    __syncthreads();

    // ---- score GEMM (K=64, bf16x3): acc = Ust @ Vl^T ----
    uint32_t UhB = (uint32_t)__cvta_generic_to_shared(sh.u.e.Uh);
    uint32_t UlB = (uint32_t)__cvta_generic_to_shared(sh.u.e.Ul);
    uint32_t VhB = (uint32_t)__cvta_generic_to_shared(sh.u.e.Vh);
    uint32_t VlB = (uint32_t)__cvta_generic_to_shared(sh.u.e.Vl);
    #pragma unroll
    for (int j = 0; j < 8; j++)
        #pragma unroll
        for (int q = 0; q < 4; q++) acc[j][q] = 0.f;
    #pragma unroll
    for (int kk = 0; kk < 4; kk++) {
        int arow = R0 + (lane & 15);
        uint32_t aoff = (uint32_t)(arow*128 + (2*kk + (lane >> 4))*16)
                        ^ ((uint32_t)(arow & 7) << 4);
        uint32_t ah[4], al[4];
        ldsm4(ah, UhB + aoff);
        ldsm4(al, UlB + aoff);
        int krow = 16*kk + (lane & 15);
        uint32_t bxor = (uint32_t)(krow & 7) << 4;
        #pragma unroll
        for (int f = 0; f < 4; f++) {
            uint32_t boff = (uint32_t)(krow*128 + (2*f + (lane >> 4))*16) ^ bxor;
            uint32_t bh[4], bl[4];
            ldsm4t(bh, VhB + boff);
            mma16816(acc[2*f],     ah, bh[0], bh[1]);
            mma16816(acc[2*f + 1], ah, bh[2], bh[3]);
            mma16816(acc[2*f],     al, bh[0], bh[1]);
            mma16816(acc[2*f + 1], al, bh[2], bh[3]);
            ldsm4t(bl, VlB + boff);
            mma16816(acc[2*f],     ah, bl[0], bl[1]);
            mma16816(acc[2*f + 1], ah, bl[2], bl[3]);
        }
    }

    // ---- warp-local softmax over 64 cols + gate scale + scattered write ----
    float m0 = -1e30f, m1 = -1e30f;
    #pragma unroll
    for (int j = 0; j < 8; j++) {
        m0 = fmaxf(m0, fmaxf(acc[j][0], acc[j][1]));
        m1 = fmaxf(m1, fmaxf(acc[j][2], acc[j][3]));
    }
    m0 = fmaxf(m0, __shfl_xor_sync(0xffffffffu, m0, 1));
    m0 = fmaxf(m0, __shfl_xor_sync(0xffffffffu, m0, 2));
    m1 = fmaxf(m1, __shfl_xor_sync(0xffffffffu, m1, 1));
    m1 = fmaxf(m1, __shfl_xor_sync(0xffffffffu, m1, 2));
    s0 = 0.f; s1 = 0.f;
    #pragma unroll
    for (int j = 0; j < 8; j++) {
        acc[j][0] = __expf(acc[j][0] - m0); acc[j][1] = __expf(acc[j][1] - m0);
        acc[j][2] = __expf(acc[j][2] - m1); acc[j][3] = __expf(acc[j][3] - m1);
        s0 += acc[j][0] + acc[j][1];
        s1 += acc[j][2] + acc[j][3];
    }
    s0 += __shfl_xor_sync(0xffffffffu, s0, 1);
    s0 += __shfl_xor_sync(0xffffffffu, s0, 2);
    s1 += __shfl_xor_sync(0xffffffffu, s1, 1);
    s1 += __shfl_xor_sync(0xffffffffu, s1, 2);
    int row0 = R0 + g, row1 = R0 + g + 8;
    float sc0 = sh.gwv[row0] / s0;
    float sc1 = sh.gwv[row1] / s1;
    bool ok0 = (base + row0) < cnt;
    bool ok1 = (base + row1) < cnt;
    float* d0 = g_out + (size_t)sh.el[row0]*LSZ;
    float* d1 = g_out + (size_t)sh.el[row1]*LSZ;
    #pragma unroll
    for (int j = 0; j < 8; j++) {
        int col = 8*j + 2*tq;
        if (ok0) *(float2*)(d0 + col) = make_float2(acc[j][0]*sc0, acc[j][1]*sc0);
        if (ok1) *(float2*)(d1 + col) = make_float2(acc[j][2]*sc1, acc[j][3]*sc1);
    }
}

// ---------------- sample: combine 2 entries, cumsum, pick, log ----------------
__global__ __launch_bounds__(256) void sample_kernel(const float* __restrict__ rnd,
                                                     float* __restrict__ out_idx,
                                                     float* __restrict__ out_lp) {
    int t = threadIdx.x, lane = t & 31, w = t >> 5;
    int n = blockIdx.x*8 + w;
    const float* b = g_out + (size_t)2*n*LSZ;
    float v0 = b[lane]      + b[64 + lane];
    float v1 = b[32 + lane] + b[96 + lane];
    float rv = rnd[n];
    float s0 = v0;
    #pragma unroll
    for (int o = 1; o < 32; o <<= 1) {
        float u = __shfl_up_sync(0xffffffffu, s0, o);
        if (lane >= o) s0 += u;
    }
    float tot0 = __shfl_sync(0xffffffffu, s0, 31);
    float s1 = v1;
    #pragma unroll
    for (int o = 1; o < 32; o <<= 1) {
        float u = __shfl_up_sync(0xffffffffu, s1, o);
        if (lane >= o) s1 += u;
    }
    s1 += tot0;
    unsigned b0 = __ballot_sync(0xffffffffu, s0 > rv);
    unsigned b1 = __ballot_sync(0xffffffffu, s1 > rv);
    int sel = b0 ? (__ffs(b0) - 1) : (b1 ? (31 + __ffs(b1)) : 0);
    float p = (sel < 32) ? __shfl_sync(0xffffffffu, v0, sel)
                         : __shfl_sync(0xffffffffu, v1, sel - 32);
    if (lane == 0) {
        out_idx[n] = (float)sel;
        out_lp[n]  = logf(p);
    }
}

// ---------------- aux loss ----------------
__global__ void aux_kernel(float* __restrict__ out_aux) {
    float s = 0.f;
    #pragma unroll
    for (int r = 0; r < RSZ; r++)
        s += (g_probsum[r] / (float)NTOK) * ((float)g_cnt[r] / (float)NTOK);
    out_aux[0] = (float)RSZ * s * 0.05f;
}

// ---------------- launch ----------------
extern "C" void kernel_launch(void* const* d_in, const int* in_sizes, int n_in,
                              void* d_out, int out_size) {
    const float* posts = (const float*)d_in[0];
    const float* reas  = (const float*)d_in[1];
    const float* llm   = (const float*)d_in[2];
    const float* rnd   = (const float*)d_in[3];
    const float* gw    = (const float*)d_in[4];
    const float* gb    = (const float*)d_in[5];
    const float* Uw    = (const float*)d_in[6];
    const float* Ub    = (const float*)d_in[7];
    const float* Vw    = (const float*)d_in[8];
    const float* Vb    = (const float*)d_in[9];
    float* out = (float*)d_out;

    static bool attr_done = false;
    if (!attr_done) {
        cudaFuncSetAttribute(proj_kernel, cudaFuncAttributeMaxDynamicSharedMemorySize,
                             (int)sizeof(ProjSmem));
        attr_done = true;
    }

    init_kernel<<<1, 32>>>();
    vl_kernel<<<dim3(LSZ, RSZ), 64>>>(llm, Vw, Vb);
    gate_kernel<<<NTOK/GTOK, 256>>>(posts, reas, gw, gb);
    proj_kernel<<<dim3(NTOK/128, RSZ), 256, sizeof(ProjSmem)>>>(posts, reas, Uw, Ub);
    sample_kernel<<<NTOK/8, 256>>>(rnd, out, out + NTOK);
    aux_kernel<<<1, 1>>>(out + 2*NTOK);
}

// round 5
// speedup vs baseline: 1.5156x; 1.4709x over previous
#include <cuda_runtime.h>
#include <cuda_bf16.h>
#include <math.h>
#include <stdint.h>

#define NTOK  65536
#define DHALF 384
#define DFULL 768
#define LSZ   64
#define HSZ   64
#define RSZ   8

// ---------------- device scratch (static; no allocations) ----------------
__device__ int   g_cnt[RSZ];
__device__ float g_probsum[RSZ];
__device__ int   g_list[RSZ*NTOK];              // entry e = 2*n + slot
__device__ float g_gate[2*NTOK];                // gate weight per entry
__device__ float g_out[(size_t)2*NTOK*LSZ];     // gate-scaled softmax scores per entry
// pre-split, pre-swizzled Vl (ldmatrix layout, [r] blocks of 64 rows x 128B)
__device__ __align__(16) char g_VhSwz[RSZ*8192];
__device__ __align__(16) char g_VlSwz[RSZ*8192];

// ---------------- helpers ----------------
__device__ __forceinline__ uint32_t packbf(float lo, float hi) {
    uint32_t d;
    asm("cvt.rn.bf16x2.f32 %0, %1, %2;" : "=r"(d) : "f"(hi), "f"(lo));
    return d;
}
__device__ __forceinline__ void split2(float x0, float x1, uint32_t& hp, uint32_t& lp) {
    hp = packbf(x0, x1);
    float h0 = __uint_as_float(hp << 16);
    float h1 = __uint_as_float(hp & 0xffff0000u);
    lp = packbf(x0 - h0, x1 - h1);
}
__device__ __forceinline__ void ldsm4(uint32_t r[4], uint32_t addr) {
    asm volatile("ldmatrix.sync.aligned.m8n8.x4.shared.b16 {%0,%1,%2,%3}, [%4];"
        : "=r"(r[0]), "=r"(r[1]), "=r"(r[2]), "=r"(r[3]) : "r"(addr));
}
__device__ __forceinline__ void ldsm4t(uint32_t r[4], uint32_t addr) {
    asm volatile("ldmatrix.sync.aligned.m8n8.x4.trans.shared.b16 {%0,%1,%2,%3}, [%4];"
        : "=r"(r[0]), "=r"(r[1]), "=r"(r[2]), "=r"(r[3]) : "r"(addr));
}
__device__ __forceinline__ void mma16816(float c[4], const uint32_t a[4],
                                         uint32_t b0, uint32_t b1) {
    asm volatile("mma.sync.aligned.m16n8k16.row.col.f32.bf16.bf16.f32 "
        "{%0,%1,%2,%3}, {%4,%5,%6,%7}, {%8,%9}, {%0,%1,%2,%3};"
        : "+f"(c[0]), "+f"(c[1]), "+f"(c[2]), "+f"(c[3])
        : "r"(a[0]), "r"(a[1]), "r"(a[2]), "r"(a[3]), "r"(b0), "r"(b1));
}

// ---------------- init ----------------
__global__ void init_kernel() {
    int t = threadIdx.x;
    if (t < RSZ) { g_cnt[t] = 0; g_probsum[t] = 0.f; }
}

// ---------------- Vl = l2norm(llm @ V_w[r] + V_b[r]); emit swizzled bf16 hi/lo -------
__global__ __launch_bounds__(64) void vl_kernel(const float* __restrict__ llm,
                                                const float* __restrict__ Vw,
                                                const float* __restrict__ Vb) {
    int l = blockIdx.x, r = blockIdx.y, h = threadIdx.x;
    __shared__ float lsm[DHALF];
    __shared__ float red[64];
    __shared__ float s_inv;
    for (int i = h; i < DHALF; i += 64) lsm[i] = llm[l*DHALF + i];
    __syncthreads();
    float acc = Vb[r*HSZ + h];
    const float* w = Vw + ((size_t)r*DHALF)*HSZ + h;
    #pragma unroll 8
    for (int d = 0; d < DHALF; d++) acc += lsm[d] * w[(size_t)d*HSZ];
    red[h] = acc*acc;
    __syncthreads();
    if (h == 0) {
        float ss = 0.f;
        #pragma unroll
        for (int i = 0; i < 64; i++) ss += red[i];
        s_inv = 1.f / fmaxf(sqrtf(ss), 1e-12f);
    }
    __syncthreads();
    float val = acc * s_inv;
    __nv_bfloat16 hb = __float2bfloat16(val);
    unsigned short hbits = __bfloat16_as_ushort(hb);
    float hf = __uint_as_float(((uint32_t)hbits) << 16);
    unsigned short lbits = __bfloat16_as_ushort(__float2bfloat16(val - hf));
    // V smem layout: row = h (128B of 64 l-values bf16), swizzled at 16B grain
    uint32_t off = (uint32_t)(h*128 + l*2) ^ ((uint32_t)(h & 7) << 4);
    *(unsigned short*)(g_VhSwz + r*8192 + off) = hbits;
    *(unsigned short*)(g_VlSwz + r*8192 + off) = lbits;
}

// ---------------- gate: logits, softmax, top-2, aggregated list build ----------------
#define GTOK 64
__global__ __launch_bounds__(256) void gate_kernel(const float* __restrict__ posts,
                                                   const float* __restrict__ reas,
                                                   const float* __restrict__ gw,
                                                   const float* __restrict__ gb) {
    __shared__ float wsm[RSZ*DFULL];   // [r][k]
    __shared__ float pblk[8][RSZ];
    __shared__ int   i1s[GTOK], i2s[GTOK];
    __shared__ int   locs[2*GTOK];
    __shared__ int   bases[RSZ];
    int t = threadIdx.x, lane = t & 31, w = t >> 5;
    for (int idx = t; idx < RSZ*DFULL; idx += 256) {
        int k = idx >> 3, r = idx & 7;
        wsm[r*DFULL + k] = gw[idx];
    }
    if (lane < RSZ) pblk[w][lane] = 0.f;
    __syncthreads();

    int nblk = blockIdx.x * GTOK;
    for (int tok = 0; tok < 8; tok++) {
        int tl = w*8 + tok;
        int n  = nblk + tl;
        float acc[RSZ];
        #pragma unroll
        for (int r = 0; r < RSZ; r++) acc[r] = 0.f;
        const float* xp = posts + (size_t)n*DHALF;
        const float* xq = reas  + (size_t)n*DHALF;
        #pragma unroll
        for (int i = 0; i < 3; i++) {
            int k = 4*lane + 128*i;
            float4 xv = *(const float4*)(xp + k);
            #pragma unroll
            for (int r = 0; r < RSZ; r++) {
                float4 wv = *(const float4*)&wsm[r*DFULL + k];
                acc[r] += xv.x*wv.x + xv.y*wv.y + xv.z*wv.z + xv.w*wv.w;
            }
        }
        #pragma unroll
        for (int i = 0; i < 3; i++) {
            int k = 4*lane + 128*i;
            float4 xv = *(const float4*)(xq + k);
            #pragma unroll
            for (int r = 0; r < RSZ; r++) {
                float4 wv = *(const float4*)&wsm[r*DFULL + DHALF + k];
                acc[r] += xv.x*wv.x + xv.y*wv.y + xv.z*wv.z + xv.w*wv.w;
            }
        }
        #pragma unroll
        for (int r = 0; r < RSZ; r++) {
            #pragma unroll
            for (int o = 16; o > 0; o >>= 1)
                acc[r] += __shfl_xor_sync(0xffffffffu, acc[r], o);
        }
        if (lane == 0) {
            float lg[RSZ];
            #pragma unroll
            for (int r = 0; r < RSZ; r++) lg[r] = acc[r] + gb[r];
            float v1 = -1e30f, v2 = -1e30f; int i1 = 0, i2 = 0;
            #pragma unroll
            for (int r = 0; r < RSZ; r++) {
                if (lg[r] > v1)      { v2 = v1; i2 = i1; v1 = lg[r]; i1 = r; }
                else if (lg[r] > v2) { v2 = lg[r]; i2 = r; }
            }
            float s = 0.f, p[RSZ];
            #pragma unroll
            for (int r = 0; r < RSZ; r++) { p[r] = expf(lg[r] - v1); s += p[r]; }
            float invs = 1.f / s;
            #pragma unroll
            for (int r = 0; r < RSZ; r++) pblk[w][r] += p[r]*invs;
            float g0 = 1.f / (1.f + expf(v2 - v1));
            g_gate[2*n]   = g0;
            g_gate[2*n+1] = 1.f - g0;
            i1s[tl] = i1; i2s[tl] = i2;
        }
    }
    __syncthreads();
    if (t < RSZ) {
        int c = 0;
        for (int e = 0; e < 2*GTOK; e++) {
            int rid = (e & 1) ? i2s[e >> 1] : i1s[e >> 1];
            if (rid == t) locs[e] = c++;
        }
        bases[t] = atomicAdd(&g_cnt[t], c);
    }
    __syncthreads();
    if (t < 2*GTOK) {
        int rid = (t & 1) ? i2s[t >> 1] : i1s[t >> 1];
        g_list[rid*NTOK + bases[rid] + locs[t]] = 2*(nblk + (t >> 1)) + (t & 1);
    }
    if (t < RSZ) {
        float s = 0.f;
        #pragma unroll
        for (int wi = 0; wi < 8; wi++) s += pblk[wi][t];
        atomicAdd(&g_probsum[t], s);
    }
}

// ---------------- proj: bf16x3 tensor-core gathered GEMM + fused epilogue ----------
struct ProjSmem {
    union {
        struct { char Ah[128*128]; char Al[128*128]; char Wh[64*128]; char Wl[64*128]; } m;
        struct { char Uh[128*128]; char Ul[128*128]; char Vh[64*128]; char Vl[64*128]; } e;
    } u;                                    // 48 KB, both phases same layout
    int   el[128];
    float gwv[128];
    float bs[64];
};

__global__ __launch_bounds__(256, 2) void proj_kernel(const float* __restrict__ posts,
                                                      const float* __restrict__ reas,
                                                      const float* __restrict__ Uw,
                                                      const float* __restrict__ Ub) {
    int r = blockIdx.y;
    int cnt = g_cnt[r];
    int base = blockIdx.x * 128;
    if (base >= cnt) return;

    extern __shared__ char smraw[];
    ProjSmem& sh = *reinterpret_cast<ProjSmem*>(smraw);

    int t = threadIdx.x, lane = t & 31, w = t >> 5;
    const int R0 = 16*w;
    const int g  = lane >> 2;      // row group within warp tile
    const int tq = lane & 3;       // col quad

    if (t < 128) {
        int i = base + t;
        int e = (i < cnt) ? g_list[r*NTOK + i] : g_list[r*NTOK + base];
        sh.el[t] = e;
        sh.gwv[t] = g_gate[e];
    }
    if (t < 64) sh.bs[t] = Ub[r*HSZ + t];
    __syncthreads();

    const float* UwR = Uw + (size_t)r*DFULL*HSZ;

    uint32_t AhB = (uint32_t)__cvta_generic_to_shared(sh.u.m.Ah);
    uint32_t AlB = (uint32_t)__cvta_generic_to_shared(sh.u.m.Al);
    uint32_t WhB = (uint32_t)__cvta_generic_to_shared(sh.u.m.Wh);
    uint32_t WlB = (uint32_t)__cvta_generic_to_shared(sh.u.m.Wl);

    // staging roles
    int srow = t >> 1, shalf = t & 1;       // X: 128 rows, 2 half-rows of 32 floats
    int wrow = t >> 2, wq = t & 3;          // W: 64 rows, 4 quarters of 16 floats
    int xn_row = sh.el[srow] >> 1;

    float acc[8][4];
    #pragma unroll
    for (int j = 0; j < 8; j++)
        #pragma unroll
        for (int q = 0; q < 4; q++) acc[j][q] = 0.f;

    for (int c = 0; c < 12; c++) {
        // ---- stage X chunk (gathered rows, fp32 -> bf16 hi/lo, swizzled) ----
        {
            const float* src = ((c < 6) ? posts + (size_t)xn_row*DHALF + c*64
                                        : reas  + (size_t)xn_row*DHALF + (c - 6)*64)
                               + shalf*32;
            uint32_t rowbase = srow*128 + shalf*64;
            uint32_t xorv = (uint32_t)(srow & 7) << 4;
            #pragma unroll
            for (int q2 = 0; q2 < 4; q2++) {
                float4 v0 = ((const float4*)src)[2*q2];
                float4 v1 = ((const float4*)src)[2*q2 + 1];
                uint32_t h0,h1,h2,h3,l0,l1,l2,l3;
                split2(v0.x, v0.y, h0, l0); split2(v0.z, v0.w, h1, l1);
                split2(v1.x, v1.y, h2, l2); split2(v1.z, v1.w, h3, l3);
                uint32_t off = (rowbase + q2*16) ^ xorv;
                *(uint4*)(sh.u.m.Ah + off) = make_uint4(h0,h1,h2,h3);
                *(uint4*)(sh.u.m.Al + off) = make_uint4(l0,l1,l2,l3);
            }
        }
        // ---- stage W chunk ----
        {
            const float* src = UwR + ((size_t)(c*64 + wrow))*HSZ + wq*16;
            uint32_t rowbase = wrow*128 + wq*32;
            uint32_t xorv = (uint32_t)(wrow & 7) << 4;
            #pragma unroll
            for (int q2 = 0; q2 < 2; q2++) {
                float4 v0 = ((const float4*)src)[2*q2];
                float4 v1 = ((const float4*)src)[2*q2 + 1];
                uint32_t h0,h1,h2,h3,l0,l1,l2,l3;
                split2(v0.x, v0.y, h0, l0); split2(v0.z, v0.w, h1, l1);
                split2(v1.x, v1.y, h2, l2); split2(v1.z, v1.w, h3, l3);
                uint32_t off = (rowbase + q2*16) ^ xorv;
                *(uint4*)(sh.u.m.Wh + off) = make_uint4(h0,h1,h2,h3);
                *(uint4*)(sh.u.m.Wl + off) = make_uint4(l0,l1,l2,l3);
            }
        }
        __syncthreads();
        // ---- tensor mainloop: 4 k16-steps, bf16x3 ----
        #pragma unroll
        for (int kk = 0; kk < 4; kk++) {
            int arow = R0 + (lane & 15);
            uint32_t aoff = (uint32_t)(arow*128 + (2*kk + (lane >> 4))*16)
                            ^ ((uint32_t)(arow & 7) << 4);
            uint32_t ah[4], al[4];
            ldsm4(ah, AhB + aoff);
            ldsm4(al, AlB + aoff);
            int krow = 16*kk + (lane & 15);
            uint32_t bxor = (uint32_t)(krow & 7) << 4;
            #pragma unroll
            for (int f = 0; f < 4; f++) {
                uint32_t boff = (uint32_t)(krow*128 + (2*f + (lane >> 4))*16) ^ bxor;
                uint32_t bh[4], bl[4];
                ldsm4t(bh, WhB + boff);
                mma16816(acc[2*f],     ah, bh[0], bh[1]);
                mma16816(acc[2*f + 1], ah, bh[2], bh[3]);
                mma16816(acc[2*f],     al, bh[0], bh[1]);
                mma16816(acc[2*f + 1], al, bh[2], bh[3]);
                ldsm4t(bl, WlB + boff);
                mma16816(acc[2*f],     ah, bl[0], bl[1]);
                mma16816(acc[2*f + 1], ah, bl[2], bl[3]);
            }
        }
        __syncthreads();
    }

    // ---- copy pre-swizzled V tiles (overlays W region; mainloop done) ----
    {
        const uint4* srcH = (const uint4*)(g_VhSwz + r*8192);
        const uint4* srcL = (const uint4*)(g_VlSwz + r*8192);
        ((uint4*)sh.u.e.Vh)[t]       = srcH[t];
        ((uint4*)sh.u.e.Vh)[t + 256] = srcH[t + 256];
        ((uint4*)sh.u.e.Vl)[t]       = srcL[t];
        ((uint4*)sh.u.e.Vl)[t + 256] = srcL[t + 256];
    }

    // ---- bias + row L2 norm (warp-local: rows R0+g and R0+g+8) ----
    float s0 = 0.f, s1 = 0.f;
    #pragma unroll
    for (int j = 0; j < 8; j++) {
        float b0 = sh.bs[8*j + 2*tq], b1 = sh.bs[8*j + 2*tq + 1];
        acc[j][0] += b0; acc[j][1] += b1;
        acc[j][2] += b0; acc[j][3] += b1;
        s0 += acc[j][0]*acc[j][0] + acc[j][1]*acc[j][1];
        s1 += acc[j][2]*acc[j][2] + acc[j][3]*acc[j][3];
    }
    s0 += __shfl_xor_sync(0xffffffffu, s0, 1);
    s0 += __shfl_xor_sync(0xffffffffu, s0, 2);
    s1 += __shfl_xor_sync(0xffffffffu, s1, 1);
    s1 += __shfl_xor_sync(0xffffffffu, s1, 2);
    float inv0 = 1.f / fmaxf(sqrtf(s0), 1e-12f);
    float inv1 = 1.f / fmaxf(sqrtf(s1), 1e-12f);

    // ---- store normalized rows as bf16 hi/lo into U tiles (A layout) ----
    {
        int rowA = R0 + g, rowB = R0 + g + 8;
        uint32_t xorA = (uint32_t)(rowA & 7) << 4;
        uint32_t xorB = (uint32_t)(rowB & 7) << 4;
        #pragma unroll
        for (int j = 0; j < 8; j++) {
            uint32_t hp, lp;
            split2(acc[j][0]*inv0, acc[j][1]*inv0, hp, lp);
            uint32_t offA = (uint32_t)(rowA*128 + 16*j + 4*tq) ^ xorA;
            *(uint32_t*)(sh.u.e.Uh + offA) = hp;
            *(uint32_t*)(sh.u.e.Ul + offA) = lp;
            split2(acc[j][2]*inv1, acc[j][3]*inv1, hp, lp);
            uint32_t offB = (uint32_t)(rowB*128 + 16*j + 4*tq) ^ xorB;
            *(uint32_t*)(sh.u.e.Uh + offB) = hp;
            *(uint32_t*)(sh.u.e.Ul + offB) = lp;
        }
    }
    __syncthreads();

    // ---- score GEMM (K=64, bf16x3): acc = Ust @ Vl^T ----
    uint32_t UhB = (uint32_t)__cvta_generic_to_shared(sh.u.e.Uh);
    uint32_t UlB = (uint32_t)__cvta_generic_to_shared(sh.u.e.Ul);
    uint32_t VhB = (uint32_t)__cvta_generic_to_shared(sh.u.e.Vh);
    uint32_t VlB = (uint32_t)__cvta_generic_to_shared(sh.u.e.Vl);
    #pragma unroll
    for (int j = 0; j < 8; j++)
        #pragma unroll
        for (int q = 0; q < 4; q++) acc[j][q] = 0.f;
    #pragma unroll
    for (int kk = 0; kk < 4; kk++) {
        int arow = R0 + (lane & 15);
        uint32_t aoff = (uint32_t)(arow*128 + (2*kk + (lane >> 4))*16)
                        ^ ((uint32_t)(arow & 7) << 4);
        uint32_t ah[4], al[4];
        ldsm4(ah, UhB + aoff);
        ldsm4(al, UlB + aoff);
        int krow = 16*kk + (lane & 15);
        uint32_t bxor = (uint32_t)(krow & 7) << 4;
        #pragma unroll
        for (int f = 0; f < 4; f++) {
            uint32_t boff = (uint32_t)(krow*128 + (2*f + (lane >> 4))*16) ^ bxor;
            uint32_t bh[4], bl[4];
            ldsm4t(bh, VhB + boff);
            mma16816(acc[2*f],     ah, bh[0], bh[1]);
            mma16816(acc[2*f + 1], ah, bh[2], bh[3]);
            mma16816(acc[2*f],     al, bh[0], bh[1]);
            mma16816(acc[2*f + 1], al, bh[2], bh[3]);
            ldsm4t(bl, VlB + boff);
            mma16816(acc[2*f],     ah, bl[0], bl[1]);
            mma16816(acc[2*f + 1], ah, bl[2], bl[3]);
        }
    }

    // ---- warp-local softmax over 64 cols + gate scale + scattered write ----
    float m0 = -1e30f, m1 = -1e30f;
    #pragma unroll
    for (int j = 0; j < 8; j++) {
        m0 = fmaxf(m0, fmaxf(acc[j][0], acc[j][1]));
        m1 = fmaxf(m1, fmaxf(acc[j][2], acc[j][3]));
    }
    m0 = fmaxf(m0, __shfl_xor_sync(0xffffffffu, m0, 1));
    m0 = fmaxf(m0, __shfl_xor_sync(0xffffffffu, m0, 2));
    m1 = fmaxf(m1, __shfl_xor_sync(0xffffffffu, m1, 1));
    m1 = fmaxf(m1, __shfl_xor_sync(0xffffffffu, m1, 2));
    s0 = 0.f; s1 = 0.f;
    #pragma unroll
    for (int j = 0; j < 8; j++) {
        acc[j][0] = __expf(acc[j][0] - m0); acc[j][1] = __expf(acc[j][1] - m0);
        acc[j][2] = __expf(acc[j][2] - m1); acc[j][3] = __expf(acc[j][3] - m1);
        s0 += acc[j][0] + acc[j][1];
        s1 += acc[j][2] + acc[j][3];
    }
    s0 += __shfl_xor_sync(0xffffffffu, s0, 1);
    s0 += __shfl_xor_sync(0xffffffffu, s0, 2);
    s1 += __shfl_xor_sync(0xffffffffu, s1, 1);
    s1 += __shfl_xor_sync(0xffffffffu, s1, 2);
    int row0 = R0 + g, row1 = R0 + g + 8;
    float sc0 = sh.gwv[row0] / s0;
    float sc1 = sh.gwv[row1] / s1;
    bool ok0 = (base + row0) < cnt;
    bool ok1 = (base + row1) < cnt;
    float* d0 = g_out + (size_t)sh.el[row0]*LSZ;
    float* d1 = g_out + (size_t)sh.el[row1]*LSZ;
    #pragma unroll
    for (int j = 0; j < 8; j++) {
        int col = 8*j + 2*tq;
        if (ok0) *(float2*)(d0 + col) = make_float2(acc[j][0]*sc0, acc[j][1]*sc0);
        if (ok1) *(float2*)(d1 + col) = make_float2(acc[j][2]*sc1, acc[j][3]*sc1);
    }
}

// ---------------- sample: combine 2 entries, cumsum, pick, log ----------------
__global__ __launch_bounds__(256) void sample_kernel(const float* __restrict__ rnd,
                                                     float* __restrict__ out_idx,
                                                     float* __restrict__ out_lp) {
    int t = threadIdx.x, lane = t & 31, w = t >> 5;
    int n = blockIdx.x*8 + w;
    const float* b = g_out + (size_t)2*n*LSZ;
    float v0 = b[lane]      + b[64 + lane];
    float v1 = b[32 + lane] + b[96 + lane];
    float rv = rnd[n];
    float s0 = v0;
    #pragma unroll
    for (int o = 1; o < 32; o <<= 1) {
        float u = __shfl_up_sync(0xffffffffu, s0, o);
        if (lane >= o) s0 += u;
    }
    float tot0 = __shfl_sync(0xffffffffu, s0, 31);
    float s1 = v1;
    #pragma unroll
    for (int o = 1; o < 32; o <<= 1) {
        float u = __shfl_up_sync(0xffffffffu, s1, o);
        if (lane >= o) s1 += u;
    }
    s1 += tot0;
    unsigned b0 = __ballot_sync(0xffffffffu, s0 > rv);
    unsigned b1 = __ballot_sync(0xffffffffu, s1 > rv);
    int sel = b0 ? (__ffs(b0) - 1) : (b1 ? (31 + __ffs(b1)) : 0);
    float p = (sel < 32) ? __shfl_sync(0xffffffffu, v0, sel)
                         : __shfl_sync(0xffffffffu, v1, sel - 32);
    if (lane == 0) {
        out_idx[n] = (float)sel;
        out_lp[n]  = logf(p);
    }
}

// ---------------- aux loss ----------------
__global__ void aux_kernel(float* __restrict__ out_aux) {
    float s = 0.f;
    #pragma unroll
    for (int r = 0; r < RSZ; r++)
        s += (g_probsum[r] / (float)NTOK) * ((float)g_cnt[r] / (float)NTOK);
    out_aux[0] = (float)RSZ * s * 0.05f;
}

// ---------------- launch ----------------
extern "C" void kernel_launch(void* const* d_in, const int* in_sizes, int n_in,
                              void* d_out, int out_size) {
    const float* posts = (const float*)d_in[0];
    const float* reas  = (const float*)d_in[1];
    const float* llm   = (const float*)d_in[2];
    const float* rnd   = (const float*)d_in[3];
    const float* gw    = (const float*)d_in[4];
    const float* gb    = (const float*)d_in[5];
    const float* Uw    = (const float*)d_in[6];
    const float* Ub    = (const float*)d_in[7];
    const float* Vw    = (const float*)d_in[8];
    const float* Vb    = (const float*)d_in[9];
    float* out = (float*)d_out;

    static bool attr_done = false;
    if (!attr_done) {
        cudaFuncSetAttribute(proj_kernel, cudaFuncAttributeMaxDynamicSharedMemorySize,
                             (int)sizeof(ProjSmem));
        attr_done = true;
    }

    init_kernel<<<1, 32>>>();
    vl_kernel<<<dim3(LSZ, RSZ), 64>>>(llm, Vw, Vb);
    gate_kernel<<<NTOK/GTOK, 256>>>(posts, reas, gw, gb);
    proj_kernel<<<dim3(NTOK/128, RSZ), 256, sizeof(ProjSmem)>>>(posts, reas, Uw, Ub);
    sample_kernel<<<NTOK/8, 256>>>(rnd, out, out + NTOK);
    aux_kernel<<<1, 1>>>(out + 2*NTOK);
}